// round 11
// baseline (speedup 1.0000x reference)
#include <cuda_runtime.h>

#define DIM 2048
#define SEQ 8192
#define NH 16
#define HD 128
#define PD 512
#define LNEPS 1e-5f
#define RSQRT_D 0.08838834764831845f  /* 1/sqrt(128) */

#define LKS 8     /* logits k-split */
#define LKC 256   /* k per chunk */
#define LKT 16    /* k per smem tile */
#define LM  256   /* rows per logits CTA */

#define CS   64   /* ctx: seq rows per chunk */
#define NCH  128  /* ctx chunks */

// ---------------- static scratch ----------------
__device__ __align__(16) float g_qW[NH * DIM];
__device__ __align__(16) float g_logP[LKS][NH * SEQ];     // 4 MB
__device__ __align__(16) float g_attn[NH * SEQ];
__device__ __align__(16) float g_partial[NCH * NH * DIM]; // 16 MB
__device__ __align__(16) float g_ctx[NH * DIM];
__device__ __align__(16) float g_x1[DIM];
__device__ __align__(16) float g_h1[PD];
__device__ __align__(16) float g_h1n[PD];
__device__ __align__(16) float g_y[DIM];

// ---- K0: qW[h][j] = sum_d q[h*128+d] * W_kv[h*128+d][j] ----
__global__ void __launch_bounds__(256) k_qw(const float* __restrict__ q,
                                            const float* __restrict__ Wkv) {
    int tid = blockIdx.x * 256 + threadIdx.x;   // 0..32767
    int h = tid >> 11;
    int j = tid & (DIM - 1);
    const float* qh = q + h * HD;
    const float* wcol = Wkv + (size_t)(h * HD) * DIM + j;
    float acc = 0.f;
#pragma unroll 16
    for (int d = 0; d < HD; d++)
        acc += qh[d] * wcol[(size_t)d * DIM];
    g_qW[tid] = acc;
}

// ---- K1: logits partials. grid (32, 8), 256 thr ----
__global__ void __launch_bounds__(256) k_logits(const float* __restrict__ x) {
    __shared__ float xs[LKT][LM + 4];   // [k][r]
    __shared__ float qs[LKC][20];       // [k][h]
    int t = threadIdx.x;
    int s0 = blockIdx.x * LM;
    int k0 = blockIdx.y * LKC;
    int rr = t >> 2;   // 0..63
    int kq = t & 3;    // 0..3
#pragma unroll
    for (int i = 0; i < 16; i++) {
        int idx = t + i * 256;           // 0..4095
        int k = idx & 255, h = idx >> 8;
        qs[k][h] = g_qW[h * DIM + k0 + k];
    }
    float acc[4][4];
#pragma unroll
    for (int i = 0; i < 4; i++)
#pragma unroll
        for (int j = 0; j < 4; j++) acc[i][j] = 0.f;
    __syncthreads();

    for (int kc = 0; kc < LKC; kc += LKT) {
#pragma unroll
        for (int m = 0; m < 4; m++) {
            int r = rr + 64 * m;
            float4 v = *reinterpret_cast<const float4*>(
                &x[(size_t)(s0 + r) * DIM + k0 + kc + kq * 4]);
            xs[kq * 4 + 0][r] = v.x;
            xs[kq * 4 + 1][r] = v.y;
            xs[kq * 4 + 2][r] = v.z;
            xs[kq * 4 + 3][r] = v.w;
        }
        __syncthreads();
#pragma unroll
        for (int k = 0; k < LKT; k++) {
            float4 xv = *reinterpret_cast<const float4*>(&xs[k][rr * 4]);
            float4 qv = *reinterpret_cast<const float4*>(&qs[kc + k][kq * 4]);
            float ax[4] = {xv.x, xv.y, xv.z, xv.w};
            float aq[4] = {qv.x, qv.y, qv.z, qv.w};
#pragma unroll
            for (int i = 0; i < 4; i++)
#pragma unroll
                for (int j = 0; j < 4; j++) acc[i][j] += ax[i] * aq[j];
        }
        __syncthreads();
    }
#pragma unroll
    for (int j = 0; j < 4; j++)
#pragma unroll
        for (int i = 0; i < 4; i++)
            g_logP[blockIdx.y][(kq * 4 + j) * SEQ + s0 + rr * 4 + i] = acc[i][j];
}

// ---- K2: softmax per head (sums k-split partials, applies 1/sqrt(d)) ----
__global__ void __launch_bounds__(1024) k_softmax() {
    __shared__ float red[32];
    int h = blockIdx.x, t = threadIdx.x;
    float vals[8];
    float m = -1e30f;
#pragma unroll
    for (int i = 0; i < 8; i++) {
        int idx = t + i * 1024;
        float v = 0.f;
#pragma unroll
        for (int ks = 0; ks < LKS; ks++) v += g_logP[ks][h * SEQ + idx];
        v *= RSQRT_D;
        vals[i] = v;
        m = fmaxf(m, v);
    }
#pragma unroll
    for (int o = 16; o; o >>= 1) m = fmaxf(m, __shfl_xor_sync(0xffffffffu, m, o));
    if ((t & 31) == 0) red[t >> 5] = m;
    __syncthreads();
    m = red[0];
#pragma unroll
    for (int i = 1; i < 32; i++) m = fmaxf(m, red[i]);

    float sum = 0.f;
#pragma unroll
    for (int i = 0; i < 8; i++) { vals[i] = __expf(vals[i] - m); sum += vals[i]; }
#pragma unroll
    for (int o = 16; o; o >>= 1) sum += __shfl_xor_sync(0xffffffffu, sum, o);
    __syncthreads();
    if ((t & 31) == 0) red[t >> 5] = sum;
    __syncthreads();
    float tot = 0.f;
#pragma unroll
    for (int i = 0; i < 32; i++) tot += red[i];
    float rinv = 1.0f / tot;
#pragma unroll
    for (int i = 0; i < 8; i++) g_attn[h * SEQ + t + i * 1024] = vals[i] * rinv;
}

// ---- K3: ctx partials = attn @ x ----
// grid (128, 2, 2): s-chunk (64 rows), j-half (1024 cols), h-half (8 heads).
// 256 thr; per thread: 4 j (float4) x 8 heads. float4 x loads, float4 attn.
__global__ void __launch_bounds__(256) k_ctx(const float* __restrict__ x) {
    __shared__ float as[8][CS];
    int t = threadIdx.x;
    int s0 = blockIdx.x * CS;
    int hb = blockIdx.z * 8;
    int j = blockIdx.y * 1024 + t * 4;

    // load attn slice: 8 heads x 64 s = 512 floats
#pragma unroll
    for (int i = 0; i < 2; i++) {
        int idx = t + i * 256;            // 0..511
        int h = idx >> 6, s = idx & 63;
        as[h][s] = g_attn[(hb + h) * SEQ + s0 + s];
    }
    __syncthreads();

    float4 acc[8];
#pragma unroll
    for (int h = 0; h < 8; h++) acc[h] = make_float4(0.f, 0.f, 0.f, 0.f);

    for (int sb = 0; sb < CS; sb += 4) {
        float4 a4[8];
#pragma unroll
        for (int h = 0; h < 8; h++)
            a4[h] = *reinterpret_cast<const float4*>(&as[h][sb]);
#pragma unroll
        for (int ss = 0; ss < 4; ss++) {
            float4 xv = *reinterpret_cast<const float4*>(
                &x[(size_t)(s0 + sb + ss) * DIM + j]);
#pragma unroll
            for (int h = 0; h < 8; h++) {
                float a = (ss == 0) ? a4[h].x : (ss == 1) ? a4[h].y
                        : (ss == 2) ? a4[h].z : a4[h].w;
                acc[h].x += a * xv.x;
                acc[h].y += a * xv.y;
                acc[h].z += a * xv.z;
                acc[h].w += a * xv.w;
            }
        }
    }
    float* P = g_partial + (size_t)blockIdx.x * NH * DIM;
#pragma unroll
    for (int h = 0; h < 8; h++)
        *reinterpret_cast<float4*>(&P[(hb + h) * DIM + j]) = acc[h];
}

// ---- K4: reduce ctx partials (float4) ----
__global__ void __launch_bounds__(256) k_ctxred() {
    int idx = blockIdx.x * 256 + threadIdx.x;  // 0..8191 (float4 units)
    float4 a = make_float4(0.f, 0.f, 0.f, 0.f);
#pragma unroll 16
    for (int c = 0; c < NCH; c++) {
        float4 p = *reinterpret_cast<const float4*>(
            &g_partial[(size_t)c * NH * DIM + idx * 4]);
        a.x += p.x; a.y += p.y; a.z += p.z; a.w += p.w;
    }
    *reinterpret_cast<float4*>(&g_ctx[idx * 4]) = a;
}

// ---- K5a: x1[i] = W_v[i] . ctx[head(i)] + b_v[i] ----
__global__ void __launch_bounds__(256) k_vproj(const float* __restrict__ Wkv,
                                               const float* __restrict__ bkv) {
    int gw = (blockIdx.x * blockDim.x + threadIdx.x) >> 5;  // 0..2047
    int l = threadIdx.x & 31;
    const float4* w4 = reinterpret_cast<const float4*>(Wkv + (size_t)(DIM + gw) * DIM);
    const float4* c4 = reinterpret_cast<const float4*>(g_ctx + (gw >> 7) * DIM);
    float a = 0.f;
#pragma unroll
    for (int i = l; i < DIM / 4; i += 32) {
        float4 wv = w4[i], cv = c4[i];
        a += wv.x * cv.x + wv.y * cv.y + wv.z * cv.z + wv.w * cv.w;
    }
#pragma unroll
    for (int o = 16; o; o >>= 1) a += __shfl_xor_sync(0xffffffffu, a, o);
    if (l == 0) g_x1[gw] = a + bkv[DIM + gw];
}

// ---- K5b: h1 = W_p1 . x1 + b_p1 ----
__global__ void __launch_bounds__(256) k_proj1(const float* __restrict__ Wp1,
                                               const float* __restrict__ bp1) {
    int gw = (blockIdx.x * blockDim.x + threadIdx.x) >> 5;  // 0..511
    int l = threadIdx.x & 31;
    const float4* w4 = reinterpret_cast<const float4*>(Wp1 + (size_t)gw * DIM);
    const float4* x4 = reinterpret_cast<const float4*>(g_x1);
    float a = 0.f;
#pragma unroll
    for (int i = l; i < DIM / 4; i += 32) {
        float4 wv = w4[i], xv = x4[i];
        a += wv.x * xv.x + wv.y * xv.y + wv.z * xv.z + wv.w * xv.w;
    }
#pragma unroll
    for (int o = 16; o; o >>= 1) a += __shfl_xor_sync(0xffffffffu, a, o);
    if (l == 0) g_h1[gw] = a + bp1[gw];
}

// ---- K5c: LayerNorm + ReLU over 512 ----
__global__ void __launch_bounds__(PD) k_ln(const float* __restrict__ lnw,
                                           const float* __restrict__ lnb) {
    __shared__ float red[16];
    int t = threadIdx.x;
    float v = g_h1[t];
    float a = v;
#pragma unroll
    for (int o = 16; o; o >>= 1) a += __shfl_xor_sync(0xffffffffu, a, o);
    if ((t & 31) == 0) red[t >> 5] = a;
    __syncthreads();
    float tot = 0.f;
#pragma unroll
    for (int i = 0; i < 16; i++) tot += red[i];
    float mu = tot * (1.0f / (float)PD);
    float dv = v - mu;
    float a2 = dv * dv;
#pragma unroll
    for (int o = 16; o; o >>= 1) a2 += __shfl_xor_sync(0xffffffffu, a2, o);
    __syncthreads();
    if ((t & 31) == 0) red[t >> 5] = a2;
    __syncthreads();
    float tv = 0.f;
#pragma unroll
    for (int i = 0; i < 16; i++) tv += red[i];
    float var = tv * (1.0f / (float)PD);
    float r = rsqrtf(var + LNEPS);
    g_h1n[t] = fmaxf(dv * r * lnw[t] + lnb[t], 0.0f);
}

// ---- K5d: y = W_p2 . relu_h1 + b_p2 ----
__global__ void __launch_bounds__(256) k_proj2(const float* __restrict__ Wp2,
                                               const float* __restrict__ bp2) {
    int gw = (blockIdx.x * blockDim.x + threadIdx.x) >> 5;  // 0..2047
    int l = threadIdx.x & 31;
    const float4* w4 = reinterpret_cast<const float4*>(Wp2 + (size_t)gw * PD);
    const float4* h4 = reinterpret_cast<const float4*>(g_h1n);
    float a = 0.f;
#pragma unroll
    for (int i = l; i < PD / 4; i += 32) {
        float4 wv = w4[i], hv = h4[i];
        a += wv.x * hv.x + wv.y * hv.y + wv.z * hv.z + wv.w * hv.w;
    }
#pragma unroll
    for (int o = 16; o; o >>= 1) a += __shfl_xor_sync(0xffffffffu, a, o);
    if (l == 0) g_y[gw] = a + bp2[gw];
}

// ---- K6: out = x + y (4 float4 per thread) ----
__global__ void __launch_bounds__(256) k_resid(const float4* __restrict__ x4,
                                               float4* __restrict__ o4) {
    int base = blockIdx.x * 1024 + threadIdx.x;
#pragma unroll
    for (int u = 0; u < 4; u++) {
        int i = base + u * 256;
        float4 xv = x4[i];
        float4 yv = *reinterpret_cast<const float4*>(&g_y[(i & 511) * 4]);
        o4[i] = make_float4(xv.x + yv.x, xv.y + yv.y, xv.z + yv.z, xv.w + yv.w);
    }
}

// ---------------- launch ----------------
extern "C" void kernel_launch(void* const* d_in, const int* in_sizes, int n_in,
                              void* d_out, int out_size) {
    const float* x   = (const float*)d_in[0];
    const float* q   = (const float*)d_in[1];
    const float* Wkv = (const float*)d_in[2];
    const float* bkv = (const float*)d_in[3];
    const float* Wp1 = (const float*)d_in[4];
    const float* bp1 = (const float*)d_in[5];
    const float* Wp2 = (const float*)d_in[6];
    const float* bp2 = (const float*)d_in[7];
    const float* lnw = (const float*)d_in[8];
    const float* lnb = (const float*)d_in[9];
    float* out = (float*)d_out;

    k_qw<<<(NH * DIM) / 256, 256>>>(q, Wkv);
    k_logits<<<dim3(SEQ / LM, LKS), 256>>>(x);
    k_softmax<<<NH, 1024>>>();
    k_ctx<<<dim3(NCH, 2, 2), 256>>>(x);
    k_ctxred<<<(NH * DIM / 4) / 256, 256>>>();
    k_vproj<<<(DIM * 32) / 256, 256>>>(Wkv, bkv);
    k_proj1<<<(PD * 32) / 256, 256>>>(Wp1, bp1);
    k_ln<<<1, PD>>>(lnw, lnb);
    k_proj2<<<(DIM * 32) / 256, 256>>>(Wp2, bp2);
    k_resid<<<(SEQ * DIM / 4 / 1024), 256>>>((const float4*)x, (float4*)out);
}

// round 12
// speedup vs baseline: 1.1083x; 1.1083x over previous
#include <cuda_runtime.h>

#define DIM 2048
#define SEQ 8192
#define NH 16
#define HD 128
#define PD 512
#define LNEPS 1e-5f
#define RSQRT_D 0.08838834764831845f  /* 1/sqrt(128) */

#define LKS 8     /* logits k-split */
#define LKC 256   /* k per chunk */
#define LKT 16    /* k per smem tile */
#define LM  256   /* rows per logits CTA */

#define CS   128  /* ctx: seq rows per chunk */
#define NCH  64   /* ctx chunks */

// ---------------- static scratch ----------------
__device__ __align__(16) float g_qW[NH * DIM];
__device__ __align__(16) float g_logP[LKS][NH * SEQ];     // 4 MB
__device__ __align__(16) float g_attn[NH * SEQ];
__device__ __align__(16) float g_partial[NCH * NH * DIM]; // 8 MB
__device__ __align__(16) float g_ctx[NH * DIM];
__device__ __align__(16) float g_x1[DIM];
__device__ __align__(16) float g_h1[PD];
__device__ __align__(16) float g_h1n[PD];
__device__ __align__(16) float g_y[DIM];

// ---- K0: qW[h][j] = sum_d q[h*128+d] * W_kv[h*128+d][j] ----
__global__ void __launch_bounds__(256) k_qw(const float* __restrict__ q,
                                            const float* __restrict__ Wkv) {
    int tid = blockIdx.x * 256 + threadIdx.x;   // 0..32767
    int h = tid >> 11;
    int j = tid & (DIM - 1);
    const float* qh = q + h * HD;
    const float* wcol = Wkv + (size_t)(h * HD) * DIM + j;
    float acc = 0.f;
#pragma unroll 16
    for (int d = 0; d < HD; d++)
        acc += qh[d] * wcol[(size_t)d * DIM];
    g_qW[tid] = acc;
}

// ---- K1: logits partials. grid (32, 8), 256 thr ----
__global__ void __launch_bounds__(256) k_logits(const float* __restrict__ x) {
    __shared__ float xs[LKT][LM + 4];   // [k][r]
    __shared__ float qs[LKC][20];       // [k][h]
    int t = threadIdx.x;
    int s0 = blockIdx.x * LM;
    int k0 = blockIdx.y * LKC;
    int rr = t >> 2;   // 0..63
    int kq = t & 3;    // 0..3
#pragma unroll
    for (int i = 0; i < 16; i++) {
        int idx = t + i * 256;           // 0..4095
        int k = idx & 255, h = idx >> 8;
        qs[k][h] = g_qW[h * DIM + k0 + k];
    }
    float acc[4][4];
#pragma unroll
    for (int i = 0; i < 4; i++)
#pragma unroll
        for (int j = 0; j < 4; j++) acc[i][j] = 0.f;
    __syncthreads();

    for (int kc = 0; kc < LKC; kc += LKT) {
#pragma unroll
        for (int m = 0; m < 4; m++) {
            int r = rr + 64 * m;
            float4 v = *reinterpret_cast<const float4*>(
                &x[(size_t)(s0 + r) * DIM + k0 + kc + kq * 4]);
            xs[kq * 4 + 0][r] = v.x;
            xs[kq * 4 + 1][r] = v.y;
            xs[kq * 4 + 2][r] = v.z;
            xs[kq * 4 + 3][r] = v.w;
        }
        __syncthreads();
#pragma unroll
        for (int k = 0; k < LKT; k++) {
            float4 xv = *reinterpret_cast<const float4*>(&xs[k][rr * 4]);
            float4 qv = *reinterpret_cast<const float4*>(&qs[kc + k][kq * 4]);
            float ax[4] = {xv.x, xv.y, xv.z, xv.w};
            float aq[4] = {qv.x, qv.y, qv.z, qv.w};
#pragma unroll
            for (int i = 0; i < 4; i++)
#pragma unroll
                for (int j = 0; j < 4; j++) acc[i][j] += ax[i] * aq[j];
        }
        __syncthreads();
    }
#pragma unroll
    for (int j = 0; j < 4; j++)
#pragma unroll
        for (int i = 0; i < 4; i++)
            g_logP[blockIdx.y][(kq * 4 + j) * SEQ + s0 + rr * 4 + i] = acc[i][j];
}

// ---- K2: softmax per head (sums k-split partials, applies 1/sqrt(d)) ----
__global__ void __launch_bounds__(1024) k_softmax() {
    __shared__ float red[32];
    int h = blockIdx.x, t = threadIdx.x;
    float vals[8];
    float m = -1e30f;
#pragma unroll
    for (int i = 0; i < 8; i++) {
        int idx = t + i * 1024;
        float v = 0.f;
#pragma unroll
        for (int ks = 0; ks < LKS; ks++) v += g_logP[ks][h * SEQ + idx];
        v *= RSQRT_D;
        vals[i] = v;
        m = fmaxf(m, v);
    }
#pragma unroll
    for (int o = 16; o; o >>= 1) m = fmaxf(m, __shfl_xor_sync(0xffffffffu, m, o));
    if ((t & 31) == 0) red[t >> 5] = m;
    __syncthreads();
    m = red[0];
#pragma unroll
    for (int i = 1; i < 32; i++) m = fmaxf(m, red[i]);

    float sum = 0.f;
#pragma unroll
    for (int i = 0; i < 8; i++) { vals[i] = __expf(vals[i] - m); sum += vals[i]; }
#pragma unroll
    for (int o = 16; o; o >>= 1) sum += __shfl_xor_sync(0xffffffffu, sum, o);
    __syncthreads();
    if ((t & 31) == 0) red[t >> 5] = sum;
    __syncthreads();
    float tot = 0.f;
#pragma unroll
    for (int i = 0; i < 32; i++) tot += red[i];
    float rinv = 1.0f / tot;
#pragma unroll
    for (int i = 0; i < 8; i++) g_attn[h * SEQ + t + i * 1024] = vals[i] * rinv;
}

// ---- K3: ctx partials = attn @ x, register double-buffer prefetch ----
// grid (64, 2, 2): s-chunk (128 rows), j-half (1024 cols), h-half (8 heads).
__global__ void __launch_bounds__(256) k_ctx(const float* __restrict__ x) {
    __shared__ float as[8][CS];
    int t = threadIdx.x;
    int s0 = blockIdx.x * CS;
    int hb = blockIdx.z * 8;
    int j = blockIdx.y * 1024 + t * 4;

    // load attn slice: 8 heads x 128 s = 1024 floats
#pragma unroll
    for (int i = 0; i < 4; i++) {
        int idx = t + i * 256;            // 0..1023
        int h = idx >> 7, s = idx & 127;
        as[h][s] = g_attn[(hb + h) * SEQ + s0 + s];
    }
    __syncthreads();

    float4 acc[8];
#pragma unroll
    for (int h = 0; h < 8; h++) acc[h] = make_float4(0.f, 0.f, 0.f, 0.f);

    const float* xb = x + (size_t)s0 * DIM + j;

    // prime: rows 0..3
    float4 xc[4];
#pragma unroll
    for (int r = 0; r < 4; r++)
        xc[r] = *reinterpret_cast<const float4*>(xb + (size_t)r * DIM);

    for (int sb = 0; sb < CS; sb += 4) {
        // prefetch next block (clamped; extra reload on last iter is discarded)
        int nsb = (sb + 4 < CS) ? (sb + 4) : sb;
        float4 xn[4];
#pragma unroll
        for (int r = 0; r < 4; r++)
            xn[r] = *reinterpret_cast<const float4*>(xb + (size_t)(nsb + r) * DIM);

        float4 a4[8];
#pragma unroll
        for (int h = 0; h < 8; h++)
            a4[h] = *reinterpret_cast<const float4*>(&as[h][sb]);

#pragma unroll
        for (int ss = 0; ss < 4; ss++) {
            float4 xv = xc[ss];
#pragma unroll
            for (int h = 0; h < 8; h++) {
                float a = (ss == 0) ? a4[h].x : (ss == 1) ? a4[h].y
                        : (ss == 2) ? a4[h].z : a4[h].w;
                acc[h].x += a * xv.x;
                acc[h].y += a * xv.y;
                acc[h].z += a * xv.z;
                acc[h].w += a * xv.w;
            }
        }
#pragma unroll
        for (int r = 0; r < 4; r++) xc[r] = xn[r];
    }

    float* P = g_partial + (size_t)blockIdx.x * NH * DIM;
#pragma unroll
    for (int h = 0; h < 8; h++)
        *reinterpret_cast<float4*>(&P[(hb + h) * DIM + j]) = acc[h];
}

// ---- K4: reduce ctx partials (float4) ----
__global__ void __launch_bounds__(256) k_ctxred() {
    int idx = blockIdx.x * 256 + threadIdx.x;  // 0..8191 (float4 units)
    float4 a = make_float4(0.f, 0.f, 0.f, 0.f);
#pragma unroll 16
    for (int c = 0; c < NCH; c++) {
        float4 p = *reinterpret_cast<const float4*>(
            &g_partial[(size_t)c * NH * DIM + idx * 4]);
        a.x += p.x; a.y += p.y; a.z += p.z; a.w += p.w;
    }
    *reinterpret_cast<float4*>(&g_ctx[idx * 4]) = a;
}

// ---- K5a: x1[i] = W_v[i] . ctx[head(i)] + b_v[i] ----
__global__ void __launch_bounds__(256) k_vproj(const float* __restrict__ Wkv,
                                               const float* __restrict__ bkv) {
    int gw = (blockIdx.x * blockDim.x + threadIdx.x) >> 5;  // 0..2047
    int l = threadIdx.x & 31;
    const float4* w4 = reinterpret_cast<const float4*>(Wkv + (size_t)(DIM + gw) * DIM);
    const float4* c4 = reinterpret_cast<const float4*>(g_ctx + (gw >> 7) * DIM);
    float a = 0.f;
#pragma unroll
    for (int i = l; i < DIM / 4; i += 32) {
        float4 wv = w4[i], cv = c4[i];
        a += wv.x * cv.x + wv.y * cv.y + wv.z * cv.z + wv.w * cv.w;
    }
#pragma unroll
    for (int o = 16; o; o >>= 1) a += __shfl_xor_sync(0xffffffffu, a, o);
    if (l == 0) g_x1[gw] = a + bkv[DIM + gw];
}

// ---- K5b: h1 = W_p1 . x1 + b_p1 ----
__global__ void __launch_bounds__(256) k_proj1(const float* __restrict__ Wp1,
                                               const float* __restrict__ bp1) {
    int gw = (blockIdx.x * blockDim.x + threadIdx.x) >> 5;  // 0..511
    int l = threadIdx.x & 31;
    const float4* w4 = reinterpret_cast<const float4*>(Wp1 + (size_t)gw * DIM);
    const float4* x4 = reinterpret_cast<const float4*>(g_x1);
    float a = 0.f;
#pragma unroll
    for (int i = l; i < DIM / 4; i += 32) {
        float4 wv = w4[i], xv = x4[i];
        a += wv.x * xv.x + wv.y * xv.y + wv.z * xv.z + wv.w * xv.w;
    }
#pragma unroll
    for (int o = 16; o; o >>= 1) a += __shfl_xor_sync(0xffffffffu, a, o);
    if (l == 0) g_h1[gw] = a + bp1[gw];
}

// ---- K5c: LayerNorm + ReLU over 512 ----
__global__ void __launch_bounds__(PD) k_ln(const float* __restrict__ lnw,
                                           const float* __restrict__ lnb) {
    __shared__ float red[16];
    int t = threadIdx.x;
    float v = g_h1[t];
    float a = v;
#pragma unroll
    for (int o = 16; o; o >>= 1) a += __shfl_xor_sync(0xffffffffu, a, o);
    if ((t & 31) == 0) red[t >> 5] = a;
    __syncthreads();
    float tot = 0.f;
#pragma unroll
    for (int i = 0; i < 16; i++) tot += red[i];
    float mu = tot * (1.0f / (float)PD);
    float dv = v - mu;
    float a2 = dv * dv;
#pragma unroll
    for (int o = 16; o; o >>= 1) a2 += __shfl_xor_sync(0xffffffffu, a2, o);
    __syncthreads();
    if ((t & 31) == 0) red[t >> 5] = a2;
    __syncthreads();
    float tv = 0.f;
#pragma unroll
    for (int i = 0; i < 16; i++) tv += red[i];
    float var = tv * (1.0f / (float)PD);
    float r = rsqrtf(var + LNEPS);
    g_h1n[t] = fmaxf(dv * r * lnw[t] + lnb[t], 0.0f);
}

// ---- K5d: y = W_p2 . relu_h1 + b_p2 ----
__global__ void __launch_bounds__(256) k_proj2(const float* __restrict__ Wp2,
                                               const float* __restrict__ bp2) {
    int gw = (blockIdx.x * blockDim.x + threadIdx.x) >> 5;  // 0..2047
    int l = threadIdx.x & 31;
    const float4* w4 = reinterpret_cast<const float4*>(Wp2 + (size_t)gw * PD);
    const float4* h4 = reinterpret_cast<const float4*>(g_h1n);
    float a = 0.f;
#pragma unroll
    for (int i = l; i < PD / 4; i += 32) {
        float4 wv = w4[i], hv = h4[i];
        a += wv.x * hv.x + wv.y * hv.y + wv.z * hv.z + wv.w * hv.w;
    }
#pragma unroll
    for (int o = 16; o; o >>= 1) a += __shfl_xor_sync(0xffffffffu, a, o);
    if (l == 0) g_y[gw] = a + bp2[gw];
}

// ---- K6: out = x + y (R5 shape: 1 float4/thread) ----
__global__ void __launch_bounds__(256) k_resid(const float4* __restrict__ x4,
                                               float4* __restrict__ o4) {
    int i = blockIdx.x * 256 + threadIdx.x;
    float4 xv = x4[i];
    float4 yv = *reinterpret_cast<const float4*>(&g_y[(i & 511) * 4]);
    o4[i] = make_float4(xv.x + yv.x, xv.y + yv.y, xv.z + yv.z, xv.w + yv.w);
}

// ---------------- launch ----------------
extern "C" void kernel_launch(void* const* d_in, const int* in_sizes, int n_in,
                              void* d_out, int out_size) {
    const float* x   = (const float*)d_in[0];
    const float* q   = (const float*)d_in[1];
    const float* Wkv = (const float*)d_in[2];
    const float* bkv = (const float*)d_in[3];
    const float* Wp1 = (const float*)d_in[4];
    const float* bp1 = (const float*)d_in[5];
    const float* Wp2 = (const float*)d_in[6];
    const float* bp2 = (const float*)d_in[7];
    const float* lnw = (const float*)d_in[8];
    const float* lnb = (const float*)d_in[9];
    float* out = (float*)d_out;

    k_qw<<<(NH * DIM) / 256, 256>>>(q, Wkv);
    k_logits<<<dim3(SEQ / LM, LKS), 256>>>(x);
    k_softmax<<<NH, 1024>>>();
    k_ctx<<<dim3(NCH, 2, 2), 256>>>(x);
    k_ctxred<<<(NH * DIM / 4) / 256, 256>>>();
    k_vproj<<<(DIM * 32) / 256, 256>>>(Wkv, bkv);
    k_proj1<<<(PD * 32) / 256, 256>>>(Wp1, bp1);
    k_ln<<<1, PD>>>(lnw, lnb);
    k_proj2<<<(DIM * 32) / 256, 256>>>(Wp2, bp2);
    k_resid<<<(SEQ * DIM / 4) / 256, 256>>>((const float4*)x, (float4*)out);
}

// round 15
// speedup vs baseline: 1.1294x; 1.0190x over previous
#include <cuda_runtime.h>

#define DIM 2048
#define SEQ 8192
#define NH 16
#define HD 128
#define PD 512
#define LNEPS 1e-5f
#define RSQRT_D 0.08838834764831845f  /* 1/sqrt(128) */

#define LKS 8     /* logits k-split */
#define LKC 256   /* k per chunk */
#define LKT 16    /* k per smem tile */
#define LM  256   /* rows per logits CTA */

#define CS   64   /* ctx: seq rows per chunk */
#define NCH  128  /* ctx chunks */

// ---------------- static scratch ----------------
__device__ __align__(16) float g_qW[NH * DIM];
__device__ __align__(16) float g_logP[LKS][NH * SEQ];     // 4 MB
__device__ __align__(16) float g_attn[NH * SEQ];
__device__ __align__(16) float g_partial[NCH * NH * DIM]; // 16 MB
__device__ __align__(16) float g_ctx[NH * DIM];
__device__ __align__(16) float g_x1[DIM];
__device__ __align__(16) float g_h1[PD];
__device__ __align__(16) float g_h1n[PD];
__device__ __align__(16) float g_y[DIM];

// ---- K0: qW[h][j] = sum_d q[h*128+d] * W_kv[h*128+d][j] ----
__global__ void __launch_bounds__(256) k_qw(const float* __restrict__ q,
                                            const float* __restrict__ Wkv) {
    int tid = blockIdx.x * 256 + threadIdx.x;   // 0..32767
    int h = tid >> 11;
    int j = tid & (DIM - 1);
    const float* qh = q + h * HD;
    const float* wcol = Wkv + (size_t)(h * HD) * DIM + j;
    float acc = 0.f;
#pragma unroll 16
    for (int d = 0; d < HD; d++)
        acc += qh[d] * wcol[(size_t)d * DIM];
    g_qW[tid] = acc;
}

// ---- K1: logits partials. grid (32, 8), 256 thr ----
__global__ void __launch_bounds__(256) k_logits(const float* __restrict__ x) {
    __shared__ float xs[LKT][LM + 4];   // [k][r]
    __shared__ float qs[LKC][20];       // [k][h]
    int t = threadIdx.x;
    int s0 = blockIdx.x * LM;
    int k0 = blockIdx.y * LKC;
    int rr = t >> 2;   // 0..63
    int kq = t & 3;    // 0..3
#pragma unroll
    for (int i = 0; i < 16; i++) {
        int idx = t + i * 256;           // 0..4095
        int k = idx & 255, h = idx >> 8;
        qs[k][h] = g_qW[h * DIM + k0 + k];
    }
    float acc[4][4];
#pragma unroll
    for (int i = 0; i < 4; i++)
#pragma unroll
        for (int j = 0; j < 4; j++) acc[i][j] = 0.f;
    __syncthreads();

    for (int kc = 0; kc < LKC; kc += LKT) {
#pragma unroll
        for (int m = 0; m < 4; m++) {
            int r = rr + 64 * m;
            float4 v = *reinterpret_cast<const float4*>(
                &x[(size_t)(s0 + r) * DIM + k0 + kc + kq * 4]);
            xs[kq * 4 + 0][r] = v.x;
            xs[kq * 4 + 1][r] = v.y;
            xs[kq * 4 + 2][r] = v.z;
            xs[kq * 4 + 3][r] = v.w;
        }
        __syncthreads();
#pragma unroll
        for (int k = 0; k < LKT; k++) {
            float4 xv = *reinterpret_cast<const float4*>(&xs[k][rr * 4]);
            float4 qv = *reinterpret_cast<const float4*>(&qs[kc + k][kq * 4]);
            float ax[4] = {xv.x, xv.y, xv.z, xv.w};
            float aq[4] = {qv.x, qv.y, qv.z, qv.w};
#pragma unroll
            for (int i = 0; i < 4; i++)
#pragma unroll
                for (int j = 0; j < 4; j++) acc[i][j] += ax[i] * aq[j];
        }
        __syncthreads();
    }
#pragma unroll
    for (int j = 0; j < 4; j++)
#pragma unroll
        for (int i = 0; i < 4; i++)
            g_logP[blockIdx.y][(kq * 4 + j) * SEQ + s0 + rr * 4 + i] = acc[i][j];
}

// ---- K2: softmax per head (sums k-split partials, applies 1/sqrt(d)) ----
__global__ void __launch_bounds__(1024) k_softmax() {
    __shared__ float red[32];
    int h = blockIdx.x, t = threadIdx.x;
    float vals[8];
    float m = -1e30f;
#pragma unroll
    for (int i = 0; i < 8; i++) {
        int idx = t + i * 1024;
        float v = 0.f;
#pragma unroll
        for (int ks = 0; ks < LKS; ks++) v += g_logP[ks][h * SEQ + idx];
        v *= RSQRT_D;
        vals[i] = v;
        m = fmaxf(m, v);
    }
#pragma unroll
    for (int o = 16; o; o >>= 1) m = fmaxf(m, __shfl_xor_sync(0xffffffffu, m, o));
    if ((t & 31) == 0) red[t >> 5] = m;
    __syncthreads();
    m = red[0];
#pragma unroll
    for (int i = 1; i < 32; i++) m = fmaxf(m, red[i]);

    float sum = 0.f;
#pragma unroll
    for (int i = 0; i < 8; i++) { vals[i] = __expf(vals[i] - m); sum += vals[i]; }
#pragma unroll
    for (int o = 16; o; o >>= 1) sum += __shfl_xor_sync(0xffffffffu, sum, o);
    __syncthreads();
    if ((t & 31) == 0) red[t >> 5] = sum;
    __syncthreads();
    float tot = 0.f;
#pragma unroll
    for (int i = 0; i < 32; i++) tot += red[i];
    float rinv = 1.0f / tot;
#pragma unroll
    for (int i = 0; i < 8; i++) g_attn[h * SEQ + t + i * 1024] = vals[i] * rinv;
}

// ---- K3: ctx partials = attn @ x, all 16 heads, single x pass ----
// grid (128, 2): s-chunk (64 rows) x j-half (1024 cols). 256 thr, 2 CTAs/SM.
__global__ void __launch_bounds__(256, 2) k_ctx(const float* __restrict__ x) {
    __shared__ float as[NH][CS];
    int t = threadIdx.x;
    int s0 = blockIdx.x * CS;
    int j = blockIdx.y * 1024 + t * 4;

    // load attn slice: 16 heads x 64 s = 1024 floats
#pragma unroll
    for (int i = 0; i < 4; i++) {
        int idx = t + i * 256;            // 0..1023
        int h = idx >> 6, s = idx & 63;
        as[h][s] = g_attn[h * SEQ + s0 + s];
    }
    __syncthreads();

    float4 acc[NH];
#pragma unroll
    for (int h = 0; h < NH; h++) acc[h] = make_float4(0.f, 0.f, 0.f, 0.f);

    const float* xb = x + (size_t)s0 * DIM + j;

    // prime: rows 0..3
    float4 xc[4];
#pragma unroll
    for (int r = 0; r < 4; r++)
        xc[r] = *reinterpret_cast<const float4*>(xb + (size_t)r * DIM);

    for (int sb = 0; sb < CS; sb += 4) {
        int nsb = (sb + 4 < CS) ? (sb + 4) : sb;
        float4 xn[4];
#pragma unroll
        for (int r = 0; r < 4; r++)
            xn[r] = *reinterpret_cast<const float4*>(xb + (size_t)(nsb + r) * DIM);

#pragma unroll
        for (int hq = 0; hq < 4; hq++) {
            float4 a4[4];
#pragma unroll
            for (int hh = 0; hh < 4; hh++)
                a4[hh] = *reinterpret_cast<const float4*>(&as[hq * 4 + hh][sb]);
#pragma unroll
            for (int ss = 0; ss < 4; ss++) {
                float4 xv = xc[ss];
#pragma unroll
                for (int hh = 0; hh < 4; hh++) {
                    float a = (ss == 0) ? a4[hh].x : (ss == 1) ? a4[hh].y
                            : (ss == 2) ? a4[hh].z : a4[hh].w;
                    acc[hq * 4 + hh].x += a * xv.x;
                    acc[hq * 4 + hh].y += a * xv.y;
                    acc[hq * 4 + hh].z += a * xv.z;
                    acc[hq * 4 + hh].w += a * xv.w;
                }
            }
        }
#pragma unroll
        for (int r = 0; r < 4; r++) xc[r] = xn[r];
    }

    float* P = g_partial + (size_t)blockIdx.x * NH * DIM;
#pragma unroll
    for (int h = 0; h < NH; h++)
        *reinterpret_cast<float4*>(&P[h * DIM + j]) = acc[h];
}

// ---- K4: reduce ctx partials (float4) ----
__global__ void __launch_bounds__(256) k_ctxred() {
    int idx = blockIdx.x * 256 + threadIdx.x;  // 0..8191 (float4 units)
    float4 a = make_float4(0.f, 0.f, 0.f, 0.f);
#pragma unroll 16
    for (int c = 0; c < NCH; c++) {
        float4 p = *reinterpret_cast<const float4*>(
            &g_partial[(size_t)c * NH * DIM + idx * 4]);
        a.x += p.x; a.y += p.y; a.z += p.z; a.w += p.w;
    }
    *reinterpret_cast<float4*>(&g_ctx[idx * 4]) = a;
}

// ---- K5a: x1[i] = W_v[i] . ctx[head(i)] + b_v[i] ----
__global__ void __launch_bounds__(256) k_vproj(const float* __restrict__ Wkv,
                                               const float* __restrict__ bkv) {
    int gw = (blockIdx.x * blockDim.x + threadIdx.x) >> 5;  // 0..2047
    int l = threadIdx.x & 31;
    const float4* w4 = reinterpret_cast<const float4*>(Wkv + (size_t)(DIM + gw) * DIM);
    const float4* c4 = reinterpret_cast<const float4*>(g_ctx + (gw >> 7) * DIM);
    float a = 0.f;
#pragma unroll
    for (int i = l; i < DIM / 4; i += 32) {
        float4 wv = w4[i], cv = c4[i];
        a += wv.x * cv.x + wv.y * cv.y + wv.z * cv.z + wv.w * cv.w;
    }
#pragma unroll
    for (int o = 16; o; o >>= 1) a += __shfl_xor_sync(0xffffffffu, a, o);
    if (l == 0) g_x1[gw] = a + bkv[DIM + gw];
}

// ---- K5b: h1 = W_p1 . x1 + b_p1 ----
__global__ void __launch_bounds__(256) k_proj1(const float* __restrict__ Wp1,
                                               const float* __restrict__ bp1) {
    int gw = (blockIdx.x * blockDim.x + threadIdx.x) >> 5;  // 0..511
    int l = threadIdx.x & 31;
    const float4* w4 = reinterpret_cast<const float4*>(Wp1 + (size_t)gw * DIM);
    const float4* x4 = reinterpret_cast<const float4*>(g_x1);
    float a = 0.f;
#pragma unroll
    for (int i = l; i < DIM / 4; i += 32) {
        float4 wv = w4[i], xv = x4[i];
        a += wv.x * xv.x + wv.y * xv.y + wv.z * xv.z + wv.w * xv.w;
    }
#pragma unroll
    for (int o = 16; o; o >>= 1) a += __shfl_xor_sync(0xffffffffu, a, o);
    if (l == 0) g_h1[gw] = a + bp1[gw];
}

// ---- K5c: LayerNorm + ReLU over 512 ----
__global__ void __launch_bounds__(PD) k_ln(const float* __restrict__ lnw,
                                           const float* __restrict__ lnb) {
    __shared__ float red[16];
    int t = threadIdx.x;
    float v = g_h1[t];
    float a = v;
#pragma unroll
    for (int o = 16; o; o >>= 1) a += __shfl_xor_sync(0xffffffffu, a, o);
    if ((t & 31) == 0) red[t >> 5] = a;
    __syncthreads();
    float tot = 0.f;
#pragma unroll
    for (int i = 0; i < 16; i++) tot += red[i];
    float mu = tot * (1.0f / (float)PD);
    float dv = v - mu;
    float a2 = dv * dv;
#pragma unroll
    for (int o = 16; o; o >>= 1) a2 += __shfl_xor_sync(0xffffffffu, a2, o);
    __syncthreads();
    if ((t & 31) == 0) red[t >> 5] = a2;
    __syncthreads();
    float tv = 0.f;
#pragma unroll
    for (int i = 0; i < 16; i++) tv += red[i];
    float var = tv * (1.0f / (float)PD);
    float r = rsqrtf(var + LNEPS);
    g_h1n[t] = fmaxf(dv * r * lnw[t] + lnb[t], 0.0f);
}

// ---- K5d: y = W_p2 . relu_h1 + b_p2 ----
__global__ void __launch_bounds__(256) k_proj2(const float* __restrict__ Wp2,
                                               const float* __restrict__ bp2) {
    int gw = (blockIdx.x * blockDim.x + threadIdx.x) >> 5;  // 0..2047
    int l = threadIdx.x & 31;
    const float4* w4 = reinterpret_cast<const float4*>(Wp2 + (size_t)gw * PD);
    const float4* h4 = reinterpret_cast<const float4*>(g_h1n);
    float a = 0.f;
#pragma unroll
    for (int i = l; i < PD / 4; i += 32) {
        float4 wv = w4[i], hv = h4[i];
        a += wv.x * hv.x + wv.y * hv.y + wv.z * hv.z + wv.w * hv.w;
    }
#pragma unroll
    for (int o = 16; o; o >>= 1) a += __shfl_xor_sync(0xffffffffu, a, o);
    if (l == 0) g_y[gw] = a + bp2[gw];
}

// ---- K6: out = x + y; streaming stores keep x resident in L2 ----
__global__ void __launch_bounds__(256) k_resid(const float4* __restrict__ x4,
                                               float4* __restrict__ o4) {
    int i = blockIdx.x * 256 + threadIdx.x;
    float4 xv = x4[i];
    float4 yv = *reinterpret_cast<const float4*>(&g_y[(i & 511) * 4]);
    float4 r = make_float4(xv.x + yv.x, xv.y + yv.y, xv.z + yv.z, xv.w + yv.w);
    __stcs(&o4[i], r);
}

// ---------------- launch ----------------
extern "C" void kernel_launch(void* const* d_in, const int* in_sizes, int n_in,
                              void* d_out, int out_size) {
    const float* x   = (const float*)d_in[0];
    const float* q   = (const float*)d_in[1];
    const float* Wkv = (const float*)d_in[2];
    const float* bkv = (const float*)d_in[3];
    const float* Wp1 = (const float*)d_in[4];
    const float* bp1 = (const float*)d_in[5];
    const float* Wp2 = (const float*)d_in[6];
    const float* bp2 = (const float*)d_in[7];
    const float* lnw = (const float*)d_in[8];
    const float* lnb = (const float*)d_in[9];
    float* out = (float*)d_out;

    k_qw<<<(NH * DIM) / 256, 256>>>(q, Wkv);
    k_logits<<<dim3(SEQ / LM, LKS), 256>>>(x);
    k_softmax<<<NH, 1024>>>();
    k_ctx<<<dim3(NCH, 2), 256>>>(x);
    k_ctxred<<<(NH * DIM / 4) / 256, 256>>>();
    k_vproj<<<(DIM * 32) / 256, 256>>>(Wkv, bkv);
    k_proj1<<<(PD * 32) / 256, 256>>>(Wp1, bp1);
    k_ln<<<1, PD>>>(lnw, lnb);
    k_proj2<<<(DIM * 32) / 256, 256>>>(Wp2, bp2);
    k_resid<<<(SEQ * DIM / 4) / 256, 256>>>((const float4*)x, (float4*)out);
}